// round 2
// baseline (speedup 1.0000x reference)
#include <cuda_runtime.h>
#include <cuda_bf16.h>
#include <math.h>

// Problem constants
#define BB 2
#define LL 192
#define HH 512
#define NHH 8
#define DPHH 64
#define MAXLEN 512
#define NDELTA 383   // deltas -191..191
#define BL (BB*LL)   // 384

// ---------------- device scratch (no allocation allowed) ----------------
__device__ float g_q [BL*HH];
__device__ float g_k [BL*HH];
__device__ float g_v [BL*HH];
__device__ float g_qv[BL*HH];
__device__ float g_qu[BL*HH];
__device__ __nv_bfloat16 g_gt[4*NDELTA*HH];  // 4 tables [383][512] bf16
__device__ float g_wt[BL*NHH*HH];            // W~ [bq][n][f]
__device__ float g_cd[BL*NHH];               // constD
__device__ float g_sa[BB*NHH*LL*LL];         // scoresA (A+C term) [b][n][q][k]
__device__ float g_x [BL*HH];                // pre-FF output

// ---------------- generic batched strided SGEMM ----------------
// C[m,n] = sum_k A[m*a_sm + k*a_sk] * B[n*b_sn + k*b_sk] + bias[n]
// Tile: 64 rows x 128 cols, 256 threads, 4x8 micro-tile.
struct GemmDesc {
    const float* A;
    const float* B;
    const float* bias;
    void*        C;
    int a_sm, a_sk, b_sn, b_sk, c_sm, M, N, K, bf16;
};
struct DescArr24 { GemmDesc d[24]; };

__global__ void __launch_bounds__(256) sgemm_b(DescArr24 gd)
{
    const GemmDesc dsc = gd.d[blockIdx.z];
    const int row0 = blockIdx.y << 6;     // 64-row tiles
    const int col0 = blockIdx.x << 7;     // 128-col tiles
    if (row0 >= dsc.M || col0 >= dsc.N) return;

    __shared__ __align__(16) float As[16][68];
    __shared__ __align__(16) float Bs[16][132];

    const int t  = threadIdx.x;
    const int tx = t & 15, ty = t >> 4;

    float acc[4][8];
    #pragma unroll
    for (int im = 0; im < 4; im++)
        #pragma unroll
        for (int jn = 0; jn < 8; jn++) acc[im][jn] = 0.f;

    const float* A = dsc.A;
    const float* B = dsc.B;

    for (int k0 = 0; k0 < dsc.K; k0 += 16) {
        #pragma unroll
        for (int e = t; e < 1024; e += 256) {
            int kk = e & 15, mm = e >> 4;
            int m = row0 + mm;
            As[kk][mm] = (m < dsc.M)
                ? A[(size_t)m * dsc.a_sm + (size_t)(k0 + kk) * dsc.a_sk] : 0.f;
        }
        #pragma unroll
        for (int e = t; e < 2048; e += 256) {
            int kk = e & 15, nn = e >> 4;
            int n = col0 + nn;
            Bs[kk][nn] = (n < dsc.N)
                ? B[(size_t)n * dsc.b_sn + (size_t)(k0 + kk) * dsc.b_sk] : 0.f;
        }
        __syncthreads();
        #pragma unroll
        for (int kk = 0; kk < 16; kk++) {
            float4 a4 = *(const float4*)&As[kk][ty << 2];
            float4 b0 = *(const float4*)&Bs[kk][tx << 3];
            float4 b1 = *(const float4*)&Bs[kk][(tx << 3) + 4];
            float av[4] = {a4.x, a4.y, a4.z, a4.w};
            float bv[8] = {b0.x, b0.y, b0.z, b0.w, b1.x, b1.y, b1.z, b1.w};
            #pragma unroll
            for (int im = 0; im < 4; im++)
                #pragma unroll
                for (int jn = 0; jn < 8; jn++)
                    acc[im][jn] += av[im] * bv[jn];
        }
        __syncthreads();
    }

    #pragma unroll
    for (int im = 0; im < 4; im++) {
        int m = row0 + (ty << 2) + im;
        if (m >= dsc.M) continue;
        #pragma unroll
        for (int jn = 0; jn < 8; jn++) {
            int n = col0 + (tx << 3) + jn;
            if (n >= dsc.N) continue;
            float r = acc[im][jn] + (dsc.bias ? dsc.bias[n] : 0.f);
            if (dsc.bf16)
                ((__nv_bfloat16*)dsc.C)[(size_t)m * dsc.c_sm + n] = __float2bfloat16(r);
            else
                ((float*)dsc.C)[(size_t)m * dsc.c_sm + n] = r;
        }
    }
}

// ---------------- fused qv/qu/constD kernel ----------------
__global__ void qvqucd_kernel(const float* __restrict__ q,
                              const float* __restrict__ vbias,
                              const float* __restrict__ ubias,
                              const float* __restrict__ br,
                              float* __restrict__ qv,
                              float* __restrict__ qu,
                              float* __restrict__ cd)
{
    const int bq = blockIdx.x;
    const int t  = threadIdx.x;
    float qx  = q[bq * 512 + t];
    float qvv = qx + vbias[t];
    qv[bq * 512 + t] = qvv;
    qu[bq * 512 + t] = qx + ubias[t];

    __shared__ float s[512];
    s[t] = qvv * br[t];
    __syncthreads();

    const int w = t >> 5, lane = t & 31;
    if (w < 8) {
        float v = s[w * 64 + lane] + s[w * 64 + 32 + lane];
        #pragma unroll
        for (int sh = 16; sh > 0; sh >>= 1)
            v += __shfl_xor_sync(0xffffffffu, v, sh);
        if (lane == 0) cd[bq * 8 + w] = v;
    }
}

// ---------------- bf16 gather helper ----------------
__device__ __forceinline__ void sum_relu8(uint4 u0, uint4 u1, uint4 u2, uint4 u3,
                                          float* z)
{
    const __nv_bfloat162* a = reinterpret_cast<const __nv_bfloat162*>(&u0);
    const __nv_bfloat162* b = reinterpret_cast<const __nv_bfloat162*>(&u1);
    const __nv_bfloat162* c = reinterpret_cast<const __nv_bfloat162*>(&u2);
    const __nv_bfloat162* d = reinterpret_cast<const __nv_bfloat162*>(&u3);
    const __nv_bfloat162 zero2 = __float2bfloat162_rn(0.f);
    #pragma unroll
    for (int j = 0; j < 4; j++) {
        __nv_bfloat162 s = __hadd2(__hadd2(a[j], b[j]), __hadd2(c[j], d[j]));
        s = __hmax2(s, zero2);
        float2 f2 = __bfloat1622float2(s);
        z[2 * j]     = f2.x;
        z[2 * j + 1] = f2.y;
    }
}

// ---------------- fused attention kernel: one CTA per (b, q) ----------------
__global__ void __launch_bounds__(256) attn_kernel(
    const float* __restrict__ vbuf,
    const __nv_bfloat16* __restrict__ gtab,
    const float* __restrict__ wt,
    const float* __restrict__ sabuf,
    const float* __restrict__ cdg,
    const int*   __restrict__ pos_s,
    const int*   __restrict__ pos_e,
    const int*   __restrict__ seq_len,
    float* __restrict__ xbuf)
{
    const int BQ = blockIdx.x;            // 0..383
    const int b  = BQ / LL;
    const int qi = BQ - b * LL;

    __shared__ __align__(16) float wts[8][512];
    __shared__ float sc[8][192];          // rel part, then attn weights
    __shared__ float sA[8][192];          // precomputed (A + C) part
    __shared__ int   ps[192], pev[192];
    __shared__ float cd[8];

    const int tid  = threadIdx.x;
    const int warp = tid >> 5;
    const int lane = tid & 31;

    for (int f = tid; f < 4096; f += 256)
        wts[f >> 9][f & 511] = wt[(size_t)BQ * 4096 + f];
    {
        const size_t sabase = (size_t)b * 8 * 36864 + (size_t)qi * 192;
        for (int e = tid; e < 1536; e += 256) {
            int n = e / 192;
            int k = e - n * 192;
            sA[n][k] = sabuf[sabase + (size_t)n * 36864 + k];
        }
    }
    if (tid < 192) { ps[tid] = pos_s[b * LL + tid]; pev[tid] = pos_e[b * LL + tid]; }
    if (tid < 8)   cd[tid] = cdg[BQ * 8 + tid];
    __syncthreads();

    const int sq = ps[qi], eq = pev[qi];
    const int slen = seq_len[b];

    const __nv_bfloat16* g0 = gtab;
    const __nv_bfloat16* g1 = gtab + 1 * NDELTA * 512;
    const __nv_bfloat16* g2 = gtab + 2 * NDELTA * 512;
    const __nv_bfloat16* g3 = gtab + 3 * NDELTA * 512;

    // each warp handles 24 contiguous k, 4 at a time (register blocked)
    const int kbeg = warp * 24;
    for (int k0 = kbeg; k0 < kbeg + 24; k0 += 4) {
        int o0[4], o1[4], o2[4], o3[4];
        #pragma unroll
        for (int kk = 0; kk < 4; kk++) {
            int sk = ps[k0 + kk], ek = pev[k0 + kk];
            o0[kk] = (sq - sk + 191) << 9;
            o1[kk] = (sq - ek + 191) << 9;
            o2[kk] = (eq - sk + 191) << 9;
            o3[kk] = (eq - ek + 191) << 9;
        }
        float acc[4][8];
        #pragma unroll
        for (int kk = 0; kk < 4; kk++)
            #pragma unroll
            for (int n = 0; n < 8; n++) acc[kk][n] = 0.f;

        #pragma unroll
        for (int i = 0; i < 2; i++) {
            const int f = (lane << 3) + (i << 8);
            float z[4][8];
            #pragma unroll
            for (int kk = 0; kk < 4; kk++) {
                uint4 u0 = *(const uint4*)(g0 + o0[kk] + f);
                uint4 u1 = *(const uint4*)(g1 + o1[kk] + f);
                uint4 u2 = *(const uint4*)(g2 + o2[kk] + f);
                uint4 u3 = *(const uint4*)(g3 + o3[kk] + f);
                sum_relu8(u0, u1, u2, u3, z[kk]);
            }
            #pragma unroll
            for (int n = 0; n < 8; n++) {
                float4 w0 = *(const float4*)&wts[n][f];
                float4 w1 = *(const float4*)&wts[n][f + 4];
                #pragma unroll
                for (int kk = 0; kk < 4; kk++) {
                    acc[kk][n] += z[kk][0] * w0.x + z[kk][1] * w0.y
                                + z[kk][2] * w0.z + z[kk][3] * w0.w
                                + z[kk][4] * w1.x + z[kk][5] * w1.y
                                + z[kk][6] * w1.z + z[kk][7] * w1.w;
                }
            }
        }

        #pragma unroll
        for (int kk = 0; kk < 4; kk++) {
            #pragma unroll
            for (int n = 0; n < 8; n++) {
                float v = acc[kk][n];
                #pragma unroll
                for (int s = 16; s > 0; s >>= 1)
                    v += __shfl_xor_sync(0xffffffffu, v, s);
                if (lane == 0) sc[n][k0 + kk] = v;
            }
        }
    }
    __syncthreads();

    // softmax: warp n handles head n over 192 keys (6 per lane)
    {
        float vals[6];
        float mx = -1e30f;
        #pragma unroll
        for (int j = 0; j < 6; j++) {
            int k = lane + (j << 5);
            float v = (sc[warp][k] + sA[warp][k] + cd[warp]) * 0.125f;
            v = (k < slen) ? v : -1e30f;
            vals[j] = v;
            mx = fmaxf(mx, v);
        }
        #pragma unroll
        for (int s = 16; s > 0; s >>= 1)
            mx = fmaxf(mx, __shfl_xor_sync(0xffffffffu, mx, s));
        float se = 0.f;
        float ev[6];
        #pragma unroll
        for (int j = 0; j < 6; j++) {
            ev[j] = (vals[j] > -1e29f) ? expf(vals[j] - mx) : 0.f;
            se += ev[j];
        }
        #pragma unroll
        for (int s = 16; s > 0; s >>= 1)
            se += __shfl_xor_sync(0xffffffffu, se, s);
        float inv = 1.f / se;
        #pragma unroll
        for (int j = 0; j < 6; j++)
            sc[warp][lane + (j << 5)] = ev[j] * inv;
    }
    __syncthreads();

    // output: thread handles 2 consecutive dims; head(f0) = tid>>5 = warp
    {
        const float* vb = vbuf + (size_t)b * LL * 512;
        const int f0 = tid << 1;
        float ox = 0.f, oy = 0.f;
        #pragma unroll 8
        for (int k = 0; k < 192; k++) {
            float a = sc[warp][k];
            float2 vv = *(const float2*)(vb + (size_t)k * 512 + f0);
            ox += a * vv.x;
            oy += a * vv.y;
        }
        *(float2*)(xbuf + (size_t)BQ * 512 + f0) = make_float2(ox, oy);
    }
}

// ---------------- launch ----------------
extern "C" void kernel_launch(void* const* d_in, const int* in_sizes, int n_in,
                              void* d_out, int out_size)
{
    // optional scalar lex_num at index 4
    int off = (n_in > 4 && in_sizes[4] == 1) ? 1 : 0;

    const float* key   = (const float*)d_in[0];
    const float* query = (const float*)d_in[1];
    const float* value = (const float*)d_in[2];
    const int*   seqlp = (const int*)  d_in[3];
    const int*   pos_s = (const int*)  d_in[4 + off];
    const int*   pos_e = (const int*)  d_in[5 + off];
    const float* pe    = (const float*)d_in[6 + off];
    const float* W_fus = (const float*)d_in[7 + off];
    const float* b_fus = (const float*)d_in[8 + off];
    const float* Wk    = (const float*)d_in[9 + off];
    const float* bk    = (const float*)d_in[10 + off];
    const float* Wq    = (const float*)d_in[11 + off];
    const float* bq    = (const float*)d_in[12 + off];
    const float* Wv    = (const float*)d_in[13 + off];
    const float* bv    = (const float*)d_in[14 + off];
    const float* Wr    = (const float*)d_in[15 + off];
    const float* br    = (const float*)d_in[16 + off];
    const float* ub    = (const float*)d_in[17 + off];
    const float* vb    = (const float*)d_in[18 + off];
    const float* Wff   = (const float*)d_in[19 + off];
    const float* bff   = (const float*)d_in[20 + off];
    float* out = (float*)d_out;

    float *p_q, *p_k, *p_v, *p_qv, *p_qu, *p_wt, *p_cd, *p_sa, *p_x;
    __nv_bfloat16* p_gt;
    cudaGetSymbolAddress((void**)&p_q,  g_q);
    cudaGetSymbolAddress((void**)&p_k,  g_k);
    cudaGetSymbolAddress((void**)&p_v,  g_v);
    cudaGetSymbolAddress((void**)&p_qv, g_qv);
    cudaGetSymbolAddress((void**)&p_qu, g_qu);
    cudaGetSymbolAddress((void**)&p_gt, g_gt);
    cudaGetSymbolAddress((void**)&p_wt, g_wt);
    cudaGetSymbolAddress((void**)&p_cd, g_cd);
    cudaGetSymbolAddress((void**)&p_sa, g_sa);
    cudaGetSymbolAddress((void**)&p_x,  g_x);

    // 1) combined: q/k/v projections (K=512) + 4 delta tables (K=256, bf16 out)
    {
        DescArr24 gd = {};
        const float* Aq[3]  = {query, key, value};
        const float* Wq3[3] = {Wq, Wk, Wv};
        const float* bq3[3] = {bq, bk, bv};
        float* Cq[3] = {p_q, p_k, p_v};
        for (int i = 0; i < 3; i++) {
            gd.d[i] = {Aq[i], Wq3[i], bq3[i], Cq[i],
                       512, 1, 512, 1, 512, BL, 512, 512, 0};
        }
        // g_t[di][f] = pe[di+321, :256] . W_fus[f, t*256 : (t+1)*256] (+b_fus on t=0)
        for (int t = 0; t < 4; t++) {
            gd.d[3 + t] = {pe + 321 * 512, W_fus + t * 256,
                           (t == 0) ? b_fus : nullptr,
                           p_gt + (size_t)t * NDELTA * 512,
                           512, 1, 1024, 1, 512, NDELTA, 512, 256, 1};
        }
        sgemm_b<<<dim3(4, 6, 7), 256>>>(gd);
    }

    // 2) fused qv = q+v_bias, qu = q+u_bias, constD = qv.br per head
    qvqucd_kernel<<<BL, 512>>>(p_q, vb, ub, br, p_qv, p_qu, p_cd);

    // 3) combined: W~ (8 descs) + scoresA (16 descs)
    {
        DescArr24 gd = {};
        // W~[bq,n,f] = sum_d qv[bq, n*64+d] * Wr[n*64+d, f]
        for (int nh = 0; nh < 8; nh++) {
            gd.d[nh] = {p_qv + nh * 64, Wr + (size_t)nh * 64 * 512, nullptr,
                        p_wt + nh * 512,
                        512, 1, 1, 512, 4096, BL, 512, 64, 0};
        }
        // scoresA[b,n,q,k] = sum_d qu[b,q,n*64+d] * k[b,k,n*64+d]
        for (int b2 = 0; b2 < 2; b2++) {
            for (int nh = 0; nh < 8; nh++) {
                int z = 8 + b2 * 8 + nh;
                gd.d[z] = {p_qu + (size_t)b2 * LL * 512 + nh * 64,
                           p_k  + (size_t)b2 * LL * 512 + nh * 64,
                           nullptr,
                           p_sa + (size_t)(b2 * 8 + nh) * LL * LL,
                           512, 1, 512, 1, LL, LL, LL, 64, 0};
            }
        }
        sgemm_b<<<dim3(4, 6, 24), 256>>>(gd);
    }

    // 4) fused attention (bf16 gathers, rel-dot, softmax, attn@v)
    attn_kernel<<<BL, 256>>>(p_v, p_gt, p_wt, p_sa, p_cd,
                             pos_s, pos_e, seqlp, p_x);

    // 5) final: out = X @ Wff^T + bff
    {
        DescArr24 gd = {};
        gd.d[0] = {p_x, Wff, bff, out, 512, 1, 512, 1, 512, BL, 512, 512, 0};
        sgemm_b<<<dim3(4, 6, 1), 256>>>(gd);
    }
}

// round 3
// speedup vs baseline: 1.1595x; 1.1595x over previous
#include <cuda_runtime.h>
#include <cuda_bf16.h>
#include <math.h>

// Problem constants
#define BB 2
#define LL 192
#define HH 512
#define NHH 8
#define DPHH 64
#define MAXLEN 512
#define NDELTA 383   // deltas -191..191
#define BL (BB*LL)   // 384

// ---------------- device scratch (no allocation allowed) ----------------
__device__ float g_q [BL*HH];
__device__ float g_k [BL*HH];
__device__ float g_v [BL*HH];
__device__ float g_qv[BL*HH];
__device__ float g_qu[BL*HH];
__device__ __nv_bfloat16 g_gt[4*NDELTA*HH];   // 4 tables [383][512] bf16
__device__ __nv_bfloat16 g_wt[BL*NHH*HH];     // W~ [bq][n][f] bf16
__device__ float g_cd[BL*NHH];                // constD
__device__ float g_sa[BB*NHH*LL*LL];          // scoresA (A+C term) [b][n][q][k]
__device__ float g_x [BL*HH];                 // pre-FF output

// ---------------- f32x2 packed helpers (Blackwell) ----------------
__device__ __forceinline__ unsigned long long pk2(float x, float y) {
    unsigned long long r;
    asm("mov.b64 %0, {%1,%2};" : "=l"(r) : "f"(x), "f"(y));
    return r;
}
__device__ __forceinline__ void fma2(unsigned long long& d,
                                     unsigned long long a,
                                     unsigned long long b) {
    asm("fma.rn.f32x2 %0, %1, %2, %0;" : "+l"(d) : "l"(a), "l"(b));
}
__device__ __forceinline__ float2 upk2(unsigned long long v) {
    float x, y;
    asm("mov.b64 {%0,%1}, %2;" : "=f"(x), "=f"(y) : "l"(v));
    return make_float2(x, y);
}

// ---------------- generic batched strided SGEMM (f32x2 inner) ----------------
// C[m,n] = sum_k A[m*a_sm + k*a_sk] * B[n*b_sn + k*b_sk] + bias[n]
// Tile: 64 rows x 128 cols, 256 threads, 4x8 micro-tile via f32x2.
struct GemmDesc {
    const float* A;
    const float* B;
    const float* bias;
    void*        C;
    int a_sm, a_sk, b_sn, b_sk, c_sm, M, N, K, bf16;
};
struct DescArr24 { GemmDesc d[24]; };

__global__ void __launch_bounds__(256) sgemm_b(DescArr24 gd)
{
    const GemmDesc dsc = gd.d[blockIdx.z];
    const int row0 = blockIdx.y << 6;     // 64-row tiles
    const int col0 = blockIdx.x << 7;     // 128-col tiles
    if (row0 >= dsc.M || col0 >= dsc.N) return;

    __shared__ __align__(16) float As[16][68];
    __shared__ __align__(16) float Bs[16][132];

    const int t  = threadIdx.x;
    const int tx = t & 15, ty = t >> 4;

    unsigned long long acc2[4][4];
    #pragma unroll
    for (int im = 0; im < 4; im++)
        #pragma unroll
        for (int jb = 0; jb < 4; jb++) acc2[im][jb] = 0ULL;

    const float* A = dsc.A;
    const float* B = dsc.B;

    for (int k0 = 0; k0 < dsc.K; k0 += 16) {
        #pragma unroll
        for (int e = t; e < 1024; e += 256) {
            int kk = e & 15, mm = e >> 4;
            int m = row0 + mm;
            As[kk][mm] = (m < dsc.M)
                ? A[(size_t)m * dsc.a_sm + (size_t)(k0 + kk) * dsc.a_sk] : 0.f;
        }
        #pragma unroll
        for (int e = t; e < 2048; e += 256) {
            int kk = e & 15, nn = e >> 4;
            int n = col0 + nn;
            Bs[kk][nn] = (n < dsc.N)
                ? B[(size_t)n * dsc.b_sn + (size_t)(k0 + kk) * dsc.b_sk] : 0.f;
        }
        __syncthreads();
        #pragma unroll
        for (int kk = 0; kk < 16; kk++) {
            float4 a4 = *(const float4*)&As[kk][ty << 2];
            float4 b0 = *(const float4*)&Bs[kk][tx << 3];
            float4 b1 = *(const float4*)&Bs[kk][(tx << 3) + 4];
            unsigned long long bb[4] = {
                pk2(b0.x, b0.y), pk2(b0.z, b0.w),
                pk2(b1.x, b1.y), pk2(b1.z, b1.w)
            };
            unsigned long long am;
            am = pk2(a4.x, a4.x);
            fma2(acc2[0][0], am, bb[0]); fma2(acc2[0][1], am, bb[1]);
            fma2(acc2[0][2], am, bb[2]); fma2(acc2[0][3], am, bb[3]);
            am = pk2(a4.y, a4.y);
            fma2(acc2[1][0], am, bb[0]); fma2(acc2[1][1], am, bb[1]);
            fma2(acc2[1][2], am, bb[2]); fma2(acc2[1][3], am, bb[3]);
            am = pk2(a4.z, a4.z);
            fma2(acc2[2][0], am, bb[0]); fma2(acc2[2][1], am, bb[1]);
            fma2(acc2[2][2], am, bb[2]); fma2(acc2[2][3], am, bb[3]);
            am = pk2(a4.w, a4.w);
            fma2(acc2[3][0], am, bb[0]); fma2(acc2[3][1], am, bb[1]);
            fma2(acc2[3][2], am, bb[2]); fma2(acc2[3][3], am, bb[3]);
        }
        __syncthreads();
    }

    #pragma unroll
    for (int im = 0; im < 4; im++) {
        int m = row0 + (ty << 2) + im;
        if (m >= dsc.M) continue;
        #pragma unroll
        for (int jb = 0; jb < 4; jb++) {
            float2 r2 = upk2(acc2[im][jb]);
            int n0 = col0 + (tx << 3) + (jb << 1);
            float rx = r2.x + (dsc.bias ? dsc.bias[n0] : 0.f);
            float ry = r2.y + (dsc.bias ? dsc.bias[n0 + 1] : 0.f);
            if (dsc.bf16) {
                __nv_bfloat16* Cb = (__nv_bfloat16*)dsc.C;
                if (n0     < dsc.N) Cb[(size_t)m * dsc.c_sm + n0]     = __float2bfloat16(rx);
                if (n0 + 1 < dsc.N) Cb[(size_t)m * dsc.c_sm + n0 + 1] = __float2bfloat16(ry);
            } else {
                float* Cf = (float*)dsc.C;
                if (n0     < dsc.N) Cf[(size_t)m * dsc.c_sm + n0]     = rx;
                if (n0 + 1 < dsc.N) Cf[(size_t)m * dsc.c_sm + n0 + 1] = ry;
            }
        }
    }
}

// ---------------- fused qv/qu/constD kernel ----------------
__global__ void qvqucd_kernel(const float* __restrict__ q,
                              const float* __restrict__ vbias,
                              const float* __restrict__ ubias,
                              const float* __restrict__ br,
                              float* __restrict__ qv,
                              float* __restrict__ qu,
                              float* __restrict__ cd)
{
    const int bq = blockIdx.x;
    const int t  = threadIdx.x;
    float qx  = q[bq * 512 + t];
    float qvv = qx + vbias[t];
    qv[bq * 512 + t] = qvv;
    qu[bq * 512 + t] = qx + ubias[t];

    __shared__ float s[512];
    s[t] = qvv * br[t];
    __syncthreads();

    const int w = t >> 5, lane = t & 31;
    if (w < 8) {
        float v = s[w * 64 + lane] + s[w * 64 + 32 + lane];
        #pragma unroll
        for (int sh = 16; sh > 0; sh >>= 1)
            v += __shfl_xor_sync(0xffffffffu, v, sh);
        if (lane == 0) cd[bq * 8 + w] = v;
    }
}

// ---------------- fused attention kernel: one CTA per (b, q) ----------------
// Warp layout for score phase: lane = (kq:2bits)(fq:3bits); each warp processes
// 4 keys at a time, 8 lanes per key splitting the 512-f dot.
__global__ void __launch_bounds__(256, 3) attn_kernel(
    const float* __restrict__ vbuf,
    const __nv_bfloat16* __restrict__ gtab,
    const __nv_bfloat16* __restrict__ wt,
    const float* __restrict__ sabuf,
    const float* __restrict__ cdg,
    const int*   __restrict__ pos_s,
    const int*   __restrict__ pos_e,
    const int*   __restrict__ seq_len,
    float* __restrict__ xbuf)
{
    const int BQ = blockIdx.x;            // 0..383
    const int b  = BQ / LL;
    const int qi = BQ - b * LL;

    __shared__ __align__(16) __nv_bfloat16 wts[8][512];   // W~ bf16, 8KB
    __shared__ float sc[8][192];          // rel score, then attn weights
    __shared__ float sA[8][192];          // precomputed (A + C)
    __shared__ int   ps[192], pev[192];
    __shared__ float cd[8];

    const int tid  = threadIdx.x;
    const int warp = tid >> 5;
    const int lane = tid & 31;

    // load W~ (4096 bf16 = 512 uint4)
    {
        const uint4* src = (const uint4*)(wt + (size_t)BQ * 4096);
        uint4* dst = (uint4*)&wts[0][0];
        for (int e = tid; e < 512; e += 256) dst[e] = src[e];
    }
    {
        const size_t sabase = (size_t)b * 8 * 36864 + (size_t)qi * 192;
        for (int e = tid; e < 1536; e += 256) {
            int n = e / 192;
            int k = e - n * 192;
            sA[n][k] = sabuf[sabase + (size_t)n * 36864 + k];
        }
    }
    if (tid < 192) { ps[tid] = pos_s[b * LL + tid]; pev[tid] = pos_e[b * LL + tid]; }
    if (tid < 8)   cd[tid] = cdg[BQ * 8 + tid];
    __syncthreads();

    const int sq = ps[qi], eq = pev[qi];
    const int slen = seq_len[b];

    const __nv_bfloat16* g0 = gtab;
    const __nv_bfloat16* g1 = gtab + 1 * NDELTA * 512;
    const __nv_bfloat16* g2 = gtab + 2 * NDELTA * 512;
    const __nv_bfloat16* g3 = gtab + 3 * NDELTA * 512;

    const int kq = lane >> 3;       // 0..3
    const int fq = lane & 7;        // 0..7
    const int fb = fq << 3;         // bf16 element offset within a 64-elem chunk
    const __nv_bfloat162 zz = __float2bfloat162_rn(0.f);
    const uint4* wrow = (const uint4*)&wts[0][0];   // 64 uint4 per head row

    const int kbeg = warp * 24;
    for (int k0 = kbeg; k0 < kbeg + 24; k0 += 4) {
        if (k0 >= slen) continue;   // warp-uniform; masked region never read
        const int k = k0 + kq;
        const int sk = ps[k], ek = pev[k];
        const __nv_bfloat16* r0 = g0 + (((sq - sk + 191) << 9) + fb);
        const __nv_bfloat16* r1 = g1 + (((sq - ek + 191) << 9) + fb);
        const __nv_bfloat16* r2 = g2 + (((eq - sk + 191) << 9) + fb);
        const __nv_bfloat16* r3 = g3 + (((eq - ek + 191) << 9) + fb);

        __nv_bfloat162 acc[8];
        #pragma unroll
        for (int n = 0; n < 8; n++) acc[n] = zz;

        #pragma unroll 2
        for (int c = 0; c < 8; c++) {
            uint4 u0 = *(const uint4*)(r0 + (c << 6));
            uint4 u1 = *(const uint4*)(r1 + (c << 6));
            uint4 u2 = *(const uint4*)(r2 + (c << 6));
            uint4 u3 = *(const uint4*)(r3 + (c << 6));
            const __nv_bfloat162* A2 = (const __nv_bfloat162*)&u0;
            const __nv_bfloat162* B2 = (const __nv_bfloat162*)&u1;
            const __nv_bfloat162* C2 = (const __nv_bfloat162*)&u2;
            const __nv_bfloat162* D2 = (const __nv_bfloat162*)&u3;
            __nv_bfloat162 z[4];
            #pragma unroll
            for (int j = 0; j < 4; j++)
                z[j] = __hmax2(__hadd2(__hadd2(A2[j], B2[j]),
                                       __hadd2(C2[j], D2[j])), zz);
            #pragma unroll
            for (int n = 0; n < 8; n++) {
                uint4 w = wrow[(n << 6) + (c << 3) + fq];
                const __nv_bfloat162* W2 = (const __nv_bfloat162*)&w;
                acc[n] = __hfma2(z[0], W2[0], acc[n]);
                acc[n] = __hfma2(z[1], W2[1], acc[n]);
                acc[n] = __hfma2(z[2], W2[2], acc[n]);
                acc[n] = __hfma2(z[3], W2[3], acc[n]);
            }
        }

        #pragma unroll
        for (int n = 0; n < 8; n++) {
            float2 f2 = __bfloat1622float2(acc[n]);
            float s = f2.x + f2.y;
            s += __shfl_xor_sync(0xffffffffu, s, 4);
            s += __shfl_xor_sync(0xffffffffu, s, 2);
            s += __shfl_xor_sync(0xffffffffu, s, 1);
            if (fq == 0) sc[n][k] = s;
        }
    }
    __syncthreads();

    // softmax: warp n handles head n over 192 keys (6 per lane)
    {
        float vals[6];
        float mx = -1e30f;
        #pragma unroll
        for (int j = 0; j < 6; j++) {
            int k = lane + (j << 5);
            float v = (sc[warp][k] + sA[warp][k] + cd[warp]) * 0.125f;
            v = (k < slen) ? v : -1e30f;
            vals[j] = v;
            mx = fmaxf(mx, v);
        }
        #pragma unroll
        for (int s = 16; s > 0; s >>= 1)
            mx = fmaxf(mx, __shfl_xor_sync(0xffffffffu, mx, s));
        float se = 0.f;
        float ev[6];
        #pragma unroll
        for (int j = 0; j < 6; j++) {
            ev[j] = (vals[j] > -1e29f) ? __expf(vals[j] - mx) : 0.f;
            se += ev[j];
        }
        #pragma unroll
        for (int s = 16; s > 0; s >>= 1)
            se += __shfl_xor_sync(0xffffffffu, se, s);
        float inv = 1.f / se;
        #pragma unroll
        for (int j = 0; j < 6; j++)
            sc[warp][lane + (j << 5)] = ev[j] * inv;
    }
    __syncthreads();

    // output: thread handles 2 consecutive dims; head(f0) = tid>>5 = warp
    {
        const int kend = min(192, (slen + 3) & ~3);
        const float* vb = vbuf + (size_t)b * LL * 512 + (tid << 1);
        unsigned long long o2 = 0ULL;
        #pragma unroll 4
        for (int k = 0; k < kend; k++) {
            float a = sc[warp][k];
            float2 vv = *(const float2*)(vb + (size_t)k * 512);
            fma2(o2, pk2(a, a), pk2(vv.x, vv.y));
        }
        float2 r = upk2(o2);
        *(float2*)(xbuf + (size_t)BQ * 512 + (tid << 1)) = r;
    }
}

// ---------------- launch ----------------
extern "C" void kernel_launch(void* const* d_in, const int* in_sizes, int n_in,
                              void* d_out, int out_size)
{
    // optional scalar lex_num at index 4
    int off = (n_in > 4 && in_sizes[4] == 1) ? 1 : 0;

    const float* key   = (const float*)d_in[0];
    const float* query = (const float*)d_in[1];
    const float* value = (const float*)d_in[2];
    const int*   seqlp = (const int*)  d_in[3];
    const int*   pos_s = (const int*)  d_in[4 + off];
    const int*   pos_e = (const int*)  d_in[5 + off];
    const float* pe    = (const float*)d_in[6 + off];
    const float* W_fus = (const float*)d_in[7 + off];
    const float* b_fus = (const float*)d_in[8 + off];
    const float* Wk    = (const float*)d_in[9 + off];
    const float* bk    = (const float*)d_in[10 + off];
    const float* Wq    = (const float*)d_in[11 + off];
    const float* bq    = (const float*)d_in[12 + off];
    const float* Wv    = (const float*)d_in[13 + off];
    const float* bv    = (const float*)d_in[14 + off];
    const float* Wr    = (const float*)d_in[15 + off];
    const float* br    = (const float*)d_in[16 + off];
    const float* ub    = (const float*)d_in[17 + off];
    const float* vb    = (const float*)d_in[18 + off];
    const float* Wff   = (const float*)d_in[19 + off];
    const float* bff   = (const float*)d_in[20 + off];
    float* out = (float*)d_out;

    float *p_q, *p_k, *p_v, *p_qv, *p_qu, *p_cd, *p_sa, *p_x;
    __nv_bfloat16 *p_gt, *p_wt;
    cudaGetSymbolAddress((void**)&p_q,  g_q);
    cudaGetSymbolAddress((void**)&p_k,  g_k);
    cudaGetSymbolAddress((void**)&p_v,  g_v);
    cudaGetSymbolAddress((void**)&p_qv, g_qv);
    cudaGetSymbolAddress((void**)&p_qu, g_qu);
    cudaGetSymbolAddress((void**)&p_gt, g_gt);
    cudaGetSymbolAddress((void**)&p_wt, g_wt);
    cudaGetSymbolAddress((void**)&p_cd, g_cd);
    cudaGetSymbolAddress((void**)&p_sa, g_sa);
    cudaGetSymbolAddress((void**)&p_x,  g_x);

    // 1) combined: q/k/v projections (K=512) + 4 delta tables (K=256, bf16 out)
    {
        DescArr24 gd = {};
        const float* Aq[3]  = {query, key, value};
        const float* Wq3[3] = {Wq, Wk, Wv};
        const float* bq3[3] = {bq, bk, bv};
        float* Cq[3] = {p_q, p_k, p_v};
        for (int i = 0; i < 3; i++) {
            gd.d[i] = {Aq[i], Wq3[i], bq3[i], Cq[i],
                       512, 1, 512, 1, 512, BL, 512, 512, 0};
        }
        // g_t[di][f] = pe[di+321, :256] . W_fus[f, t*256 : (t+1)*256] (+b_fus on t=0)
        for (int t = 0; t < 4; t++) {
            gd.d[3 + t] = {pe + 321 * 512, W_fus + t * 256,
                           (t == 0) ? b_fus : nullptr,
                           p_gt + (size_t)t * NDELTA * 512,
                           512, 1, 1024, 1, 512, NDELTA, 512, 256, 1};
        }
        sgemm_b<<<dim3(4, 6, 7), 256>>>(gd);
    }

    // 2) fused qv = q+v_bias, qu = q+u_bias, constD = qv.br per head
    qvqucd_kernel<<<BL, 512>>>(p_q, vb, ub, br, p_qv, p_qu, p_cd);

    // 3) combined: W~ (8 descs, bf16 out) + scoresA (16 descs)
    {
        DescArr24 gd = {};
        // W~[bq,n,f] = sum_d qv[bq, n*64+d] * Wr[n*64+d, f]
        for (int nh = 0; nh < 8; nh++) {
            gd.d[nh] = {p_qv + nh * 64, Wr + (size_t)nh * 64 * 512, nullptr,
                        p_wt + nh * 512,
                        512, 1, 1, 512, 4096, BL, 512, 64, 1};
        }
        // scoresA[b,n,q,k] = sum_d qu[b,q,n*64+d] * k[b,k,n*64+d]
        for (int b2 = 0; b2 < 2; b2++) {
            for (int nh = 0; nh < 8; nh++) {
                int z = 8 + b2 * 8 + nh;
                gd.d[z] = {p_qu + (size_t)b2 * LL * 512 + nh * 64,
                           p_k  + (size_t)b2 * LL * 512 + nh * 64,
                           nullptr,
                           p_sa + (size_t)(b2 * 8 + nh) * LL * LL,
                           512, 1, 512, 1, LL, LL, LL, 64, 0};
            }
        }
        sgemm_b<<<dim3(4, 6, 24), 256>>>(gd);
    }

    // 4) fused attention (bf16 gathers + bf16 W~ dot, softmax, attn@v)
    attn_kernel<<<BL, 256>>>(p_v, p_gt, p_wt, p_sa, p_cd,
                             pos_s, pos_e, seqlp, p_x);

    // 5) final: out = X @ Wff^T + bff
    {
        DescArr24 gd = {};
        gd.d[0] = {p_x, Wff, bff, out, 512, 1, 512, 1, 512, BL, 512, 512, 0};
        sgemm_b<<<dim3(4, 6, 1), 256>>>(gd);
    }
}

// round 4
// speedup vs baseline: 1.7223x; 1.4854x over previous
#include <cuda_runtime.h>
#include <cuda_bf16.h>
#include <math.h>

// Problem constants
#define BB 2
#define LL 192
#define HH 512
#define NHH 8
#define DPHH 64
#define MAXLEN 512
#define NDELTA 383   // deltas -191..191
#define BL (BB*LL)   // 384

// ---------------- device scratch (no allocation allowed) ----------------
__device__ float g_q [BL*HH];
__device__ float g_k [BL*HH];
__device__ float g_v [BL*HH];
__device__ float g_qv[BL*HH];
__device__ float g_qu[BL*HH];
__device__ __nv_bfloat16 g_gt[4*NDELTA*HH];   // 4 tables [383][512] bf16
__device__ __nv_bfloat16 g_wt[BL*NHH*HH];     // W~ [bq][n][f] bf16
__device__ float g_cd[BL*NHH];                // constD
__device__ float g_sa[BB*NHH*LL*LL];          // scoresA (A+C term) [b][n][q][k]
__device__ float g_x [BL*HH];                 // pre-FF output

// ---------------- f32x2 packed helpers (Blackwell) ----------------
__device__ __forceinline__ unsigned long long pk2(float x, float y) {
    unsigned long long r;
    asm("mov.b64 %0, {%1,%2};" : "=l"(r) : "f"(x), "f"(y));
    return r;
}
__device__ __forceinline__ void fma2(unsigned long long& d,
                                     unsigned long long a,
                                     unsigned long long b) {
    asm("fma.rn.f32x2 %0, %1, %2, %0;" : "+l"(d) : "l"(a), "l"(b));
}
__device__ __forceinline__ float2 upk2(unsigned long long v) {
    float x, y;
    asm("mov.b64 {%0,%1}, %2;" : "=f"(x), "=f"(y) : "l"(v));
    return make_float2(x, y);
}

// ---------------- generic batched strided SGEMM ----------------
// C[m,n] = sum_k A[m*a_sm + k*a_sk] * B[n*b_sn + k*b_sk] + bias[n]
// Tile: 32 rows x 64 cols, 256 threads, 2x4 micro-tile (f32x2),
// register-prefetch double buffering. K must be a multiple of 16 (true here).
struct GemmDesc {
    const float* A;
    const float* B;
    const float* bias;
    void*        C;
    int a_sm, a_sk, b_sn, b_sk, c_sm, M, N, K, bf16;
};
struct DescArr24 { GemmDesc d[24]; };

__global__ void __launch_bounds__(256) sgemm_b(DescArr24 gd)
{
    const GemmDesc dsc = gd.d[blockIdx.z];
    const int row0 = blockIdx.y << 5;     // 32-row tiles
    const int col0 = blockIdx.x << 6;     // 64-col tiles
    if (row0 >= dsc.M || col0 >= dsc.N) return;

    __shared__ __align__(16) float As[16][34];
    __shared__ __align__(16) float Bs[16][68];

    const int t  = threadIdx.x;
    const int tx = t & 15, ty = t >> 4;

    // A-load mapping: element e in [0,512): kk=e&15, mm=e>>4 (2 per thread)
    // B-load mapping: element e in [0,1024): kk=e&15, nn=e>>4 (4 per thread)
    const int a_kk0 = t & 15,          a_mm0 = t >> 4;          // e = t
    const int a_mm1 = a_mm0 + 16;                               // e = t+256
    const int b_kk0 = t & 15,          b_nn0 = t >> 4;          // e = t
    const int am0ok = (row0 + a_mm0) < dsc.M;
    const int am1ok = (row0 + a_mm1) < dsc.M;
    const float* Aad0 = dsc.A + (size_t)(row0 + a_mm0) * dsc.a_sm + (size_t)a_kk0 * dsc.a_sk;
    const float* Aad1 = dsc.A + (size_t)(row0 + a_mm1) * dsc.a_sm + (size_t)a_kk0 * dsc.a_sk;
    const float* Bad[4];
    int bok[4];
    #pragma unroll
    for (int i = 0; i < 4; i++) {
        int nn = b_nn0 + 16 * i;
        bok[i] = (col0 + nn) < dsc.N;
        Bad[i] = dsc.B + (size_t)(col0 + nn) * dsc.b_sn + (size_t)b_kk0 * dsc.b_sk;
    }
    const size_t aK = (size_t)dsc.a_sk * 16;
    const size_t bK = (size_t)dsc.b_sk * 16;

    unsigned long long acc2[2][2] = {{0ULL, 0ULL}, {0ULL, 0ULL}};

    // prefetch chunk 0
    float a_r[2], b_r[4];
    a_r[0] = am0ok ? *Aad0 : 0.f;
    a_r[1] = am1ok ? *Aad1 : 0.f;
    #pragma unroll
    for (int i = 0; i < 4; i++) b_r[i] = bok[i] ? *Bad[i] : 0.f;

    for (int k0 = 0; k0 < dsc.K; k0 += 16) {
        As[a_kk0][a_mm0] = a_r[0];
        As[a_kk0][a_mm1] = a_r[1];
        #pragma unroll
        for (int i = 0; i < 4; i++) Bs[b_kk0][b_nn0 + 16 * i] = b_r[i];
        __syncthreads();

        if (k0 + 16 < dsc.K) {
            Aad0 += aK; Aad1 += aK;
            a_r[0] = am0ok ? *Aad0 : 0.f;
            a_r[1] = am1ok ? *Aad1 : 0.f;
            #pragma unroll
            for (int i = 0; i < 4; i++) {
                Bad[i] += bK;
                b_r[i] = bok[i] ? *Bad[i] : 0.f;
            }
        }

        #pragma unroll
        for (int kk = 0; kk < 16; kk++) {
            float2 a2 = *(const float2*)&As[kk][ty << 1];
            float4 b4 = *(const float4*)&Bs[kk][tx << 2];
            unsigned long long b01 = pk2(b4.x, b4.y);
            unsigned long long b23 = pk2(b4.z, b4.w);
            unsigned long long ax = pk2(a2.x, a2.x);
            unsigned long long ay = pk2(a2.y, a2.y);
            fma2(acc2[0][0], ax, b01);
            fma2(acc2[0][1], ax, b23);
            fma2(acc2[1][0], ay, b01);
            fma2(acc2[1][1], ay, b23);
        }
        __syncthreads();
    }

    #pragma unroll
    for (int im = 0; im < 2; im++) {
        int m = row0 + (ty << 1) + im;
        if (m >= dsc.M) continue;
        #pragma unroll
        for (int jb = 0; jb < 2; jb++) {
            float2 r2 = upk2(acc2[im][jb]);
            int n0 = col0 + (tx << 2) + (jb << 1);
            float rx = r2.x + (dsc.bias ? dsc.bias[n0] : 0.f);
            float ry = r2.y + (dsc.bias ? dsc.bias[n0 + 1] : 0.f);
            if (dsc.bf16) {
                __nv_bfloat16* Cb = (__nv_bfloat16*)dsc.C;
                if (n0     < dsc.N) Cb[(size_t)m * dsc.c_sm + n0]     = __float2bfloat16(rx);
                if (n0 + 1 < dsc.N) Cb[(size_t)m * dsc.c_sm + n0 + 1] = __float2bfloat16(ry);
            } else {
                float* Cf = (float*)dsc.C;
                if (n0     < dsc.N) Cf[(size_t)m * dsc.c_sm + n0]     = rx;
                if (n0 + 1 < dsc.N) Cf[(size_t)m * dsc.c_sm + n0 + 1] = ry;
            }
        }
    }
}

// ---------------- fused qv/qu/constD kernel ----------------
__global__ void qvqucd_kernel(const float* __restrict__ q,
                              const float* __restrict__ vbias,
                              const float* __restrict__ ubias,
                              const float* __restrict__ br,
                              float* __restrict__ qv,
                              float* __restrict__ qu,
                              float* __restrict__ cd)
{
    const int bq = blockIdx.x;
    const int t  = threadIdx.x;
    float qx  = q[bq * 512 + t];
    float qvv = qx + vbias[t];
    qv[bq * 512 + t] = qvv;
    qu[bq * 512 + t] = qx + ubias[t];

    __shared__ float s[512];
    s[t] = qvv * br[t];
    __syncthreads();

    const int w = t >> 5, lane = t & 31;
    if (w < 8) {
        float v = s[w * 64 + lane] + s[w * 64 + 32 + lane];
        #pragma unroll
        for (int sh = 16; sh > 0; sh >>= 1)
            v += __shfl_xor_sync(0xffffffffu, v, sh);
        if (lane == 0) cd[bq * 8 + w] = v;
    }
}

// ---------------- fused attention kernel: one CTA per (b, q) ----------------
// Warp layout for score phase: lane = (kq:2bits)(fq:3bits); each warp processes
// 4 keys at a time, 8 lanes per key splitting the 512-f dot.
__global__ void __launch_bounds__(256, 3) attn_kernel(
    const float* __restrict__ vbuf,
    const __nv_bfloat16* __restrict__ gtab,
    const __nv_bfloat16* __restrict__ wt,
    const float* __restrict__ sabuf,
    const float* __restrict__ cdg,
    const int*   __restrict__ pos_s,
    const int*   __restrict__ pos_e,
    const int*   __restrict__ seq_len,
    float* __restrict__ xbuf)
{
    const int BQ = blockIdx.x;            // 0..383
    const int b  = BQ / LL;
    const int qi = BQ - b * LL;

    __shared__ __align__(16) __nv_bfloat16 wts[8][512];   // W~ bf16, 8KB
    __shared__ float sc[8][192];          // rel score, then attn weights
    __shared__ float sA[8][192];          // precomputed (A + C)
    __shared__ int   ps[192], pev[192];
    __shared__ float cd[8];

    const int tid  = threadIdx.x;
    const int warp = tid >> 5;
    const int lane = tid & 31;

    // load W~ (4096 bf16 = 512 uint4)
    {
        const uint4* src = (const uint4*)(wt + (size_t)BQ * 4096);
        uint4* dst = (uint4*)&wts[0][0];
        for (int e = tid; e < 512; e += 256) dst[e] = src[e];
    }
    {
        const size_t sabase = (size_t)b * 8 * 36864 + (size_t)qi * 192;
        for (int e = tid; e < 1536; e += 256) {
            int n = e / 192;
            int k = e - n * 192;
            sA[n][k] = sabuf[sabase + (size_t)n * 36864 + k];
        }
    }
    if (tid < 192) { ps[tid] = pos_s[b * LL + tid]; pev[tid] = pos_e[b * LL + tid]; }
    if (tid < 8)   cd[tid] = cdg[BQ * 8 + tid];
    __syncthreads();

    const int sq = ps[qi], eq = pev[qi];
    const int slen = seq_len[b];

    const __nv_bfloat16* g0 = gtab;
    const __nv_bfloat16* g1 = gtab + 1 * NDELTA * 512;
    const __nv_bfloat16* g2 = gtab + 2 * NDELTA * 512;
    const __nv_bfloat16* g3 = gtab + 3 * NDELTA * 512;

    const int kq = lane >> 3;       // 0..3
    const int fq = lane & 7;        // 0..7
    const int fb = fq << 3;         // bf16 element offset within a 64-elem chunk
    const __nv_bfloat162 zz = __float2bfloat162_rn(0.f);
    const uint4* wrow = (const uint4*)&wts[0][0];   // 64 uint4 per head row

    const int kbeg = warp * 24;
    for (int k0 = kbeg; k0 < kbeg + 24; k0 += 4) {
        if (k0 >= slen) continue;   // warp-uniform; masked region never read
        const int k = k0 + kq;
        const int sk = ps[k], ek = pev[k];
        const __nv_bfloat16* r0 = g0 + (((sq - sk + 191) << 9) + fb);
        const __nv_bfloat16* r1 = g1 + (((sq - ek + 191) << 9) + fb);
        const __nv_bfloat16* r2 = g2 + (((eq - sk + 191) << 9) + fb);
        const __nv_bfloat16* r3 = g3 + (((eq - ek + 191) << 9) + fb);

        __nv_bfloat162 acc[8];
        #pragma unroll
        for (int n = 0; n < 8; n++) acc[n] = zz;

        #pragma unroll 2
        for (int c = 0; c < 8; c++) {
            uint4 u0 = *(const uint4*)(r0 + (c << 6));
            uint4 u1 = *(const uint4*)(r1 + (c << 6));
            uint4 u2 = *(const uint4*)(r2 + (c << 6));
            uint4 u3 = *(const uint4*)(r3 + (c << 6));
            const __nv_bfloat162* A2 = (const __nv_bfloat162*)&u0;
            const __nv_bfloat162* B2 = (const __nv_bfloat162*)&u1;
            const __nv_bfloat162* C2 = (const __nv_bfloat162*)&u2;
            const __nv_bfloat162* D2 = (const __nv_bfloat162*)&u3;
            __nv_bfloat162 z[4];
            #pragma unroll
            for (int j = 0; j < 4; j++)
                z[j] = __hmax2(__hadd2(__hadd2(A2[j], B2[j]),
                                       __hadd2(C2[j], D2[j])), zz);
            #pragma unroll
            for (int n = 0; n < 8; n++) {
                uint4 w = wrow[(n << 6) + (c << 3) + fq];
                const __nv_bfloat162* W2 = (const __nv_bfloat162*)&w;
                acc[n] = __hfma2(z[0], W2[0], acc[n]);
                acc[n] = __hfma2(z[1], W2[1], acc[n]);
                acc[n] = __hfma2(z[2], W2[2], acc[n]);
                acc[n] = __hfma2(z[3], W2[3], acc[n]);
            }
        }

        #pragma unroll
        for (int n = 0; n < 8; n++) {
            float2 f2 = __bfloat1622float2(acc[n]);
            float s = f2.x + f2.y;
            s += __shfl_xor_sync(0xffffffffu, s, 4);
            s += __shfl_xor_sync(0xffffffffu, s, 2);
            s += __shfl_xor_sync(0xffffffffu, s, 1);
            if (fq == 0) sc[n][k] = s;
        }
    }
    __syncthreads();

    // softmax: warp n handles head n over 192 keys (6 per lane)
    {
        float vals[6];
        float mx = -1e30f;
        #pragma unroll
        for (int j = 0; j < 6; j++) {
            int k = lane + (j << 5);
            float v = (sc[warp][k] + sA[warp][k] + cd[warp]) * 0.125f;
            v = (k < slen) ? v : -1e30f;
            vals[j] = v;
            mx = fmaxf(mx, v);
        }
        #pragma unroll
        for (int s = 16; s > 0; s >>= 1)
            mx = fmaxf(mx, __shfl_xor_sync(0xffffffffu, mx, s));
        float se = 0.f;
        float ev[6];
        #pragma unroll
        for (int j = 0; j < 6; j++) {
            ev[j] = (vals[j] > -1e29f) ? __expf(vals[j] - mx) : 0.f;
            se += ev[j];
        }
        #pragma unroll
        for (int s = 16; s > 0; s >>= 1)
            se += __shfl_xor_sync(0xffffffffu, se, s);
        float inv = 1.f / se;
        #pragma unroll
        for (int j = 0; j < 6; j++)
            sc[warp][lane + (j << 5)] = ev[j] * inv;
    }
    __syncthreads();

    // output: thread handles 2 consecutive dims; head(f0) = tid>>5 = warp
    {
        const int kend = min(192, (slen + 3) & ~3);
        const float* vb = vbuf + (size_t)b * LL * 512 + (tid << 1);
        unsigned long long o2 = 0ULL;
        #pragma unroll 4
        for (int k = 0; k < kend; k++) {
            float a = sc[warp][k];
            float2 vv = *(const float2*)(vb + (size_t)k * 512);
            fma2(o2, pk2(a, a), pk2(vv.x, vv.y));
        }
        float2 r = upk2(o2);
        *(float2*)(xbuf + (size_t)BQ * 512 + (tid << 1)) = r;
    }
}

// ---------------- launch ----------------
extern "C" void kernel_launch(void* const* d_in, const int* in_sizes, int n_in,
                              void* d_out, int out_size)
{
    // optional scalar lex_num at index 4
    int off = (n_in > 4 && in_sizes[4] == 1) ? 1 : 0;

    const float* key   = (const float*)d_in[0];
    const float* query = (const float*)d_in[1];
    const float* value = (const float*)d_in[2];
    const int*   seqlp = (const int*)  d_in[3];
    const int*   pos_s = (const int*)  d_in[4 + off];
    const int*   pos_e = (const int*)  d_in[5 + off];
    const float* pe    = (const float*)d_in[6 + off];
    const float* W_fus = (const float*)d_in[7 + off];
    const float* b_fus = (const float*)d_in[8 + off];
    const float* Wk    = (const float*)d_in[9 + off];
    const float* bk    = (const float*)d_in[10 + off];
    const float* Wq    = (const float*)d_in[11 + off];
    const float* bq    = (const float*)d_in[12 + off];
    const float* Wv    = (const float*)d_in[13 + off];
    const float* bv    = (const float*)d_in[14 + off];
    const float* Wr    = (const float*)d_in[15 + off];
    const float* br    = (const float*)d_in[16 + off];
    const float* ub    = (const float*)d_in[17 + off];
    const float* vb    = (const float*)d_in[18 + off];
    const float* Wff   = (const float*)d_in[19 + off];
    const float* bff   = (const float*)d_in[20 + off];
    float* out = (float*)d_out;

    float *p_q, *p_k, *p_v, *p_qv, *p_qu, *p_cd, *p_sa, *p_x;
    __nv_bfloat16 *p_gt, *p_wt;
    cudaGetSymbolAddress((void**)&p_q,  g_q);
    cudaGetSymbolAddress((void**)&p_k,  g_k);
    cudaGetSymbolAddress((void**)&p_v,  g_v);
    cudaGetSymbolAddress((void**)&p_qv, g_qv);
    cudaGetSymbolAddress((void**)&p_qu, g_qu);
    cudaGetSymbolAddress((void**)&p_gt, g_gt);
    cudaGetSymbolAddress((void**)&p_wt, g_wt);
    cudaGetSymbolAddress((void**)&p_cd, g_cd);
    cudaGetSymbolAddress((void**)&p_sa, g_sa);
    cudaGetSymbolAddress((void**)&p_x,  g_x);

    // 1) combined: q/k/v projections (K=512) + 4 delta tables (K=256, bf16 out)
    {
        DescArr24 gd = {};
        const float* Aq[3]  = {query, key, value};
        const float* Wq3[3] = {Wq, Wk, Wv};
        const float* bq3[3] = {bq, bk, bv};
        float* Cq[3] = {p_q, p_k, p_v};
        for (int i = 0; i < 3; i++) {
            gd.d[i] = {Aq[i], Wq3[i], bq3[i], Cq[i],
                       512, 1, 512, 1, 512, BL, 512, 512, 0};
        }
        // g_t[di][f] = pe[di+321, :256] . W_fus[f, t*256 : (t+1)*256] (+b_fus on t=0)
        for (int t = 0; t < 4; t++) {
            gd.d[3 + t] = {pe + 321 * 512, W_fus + t * 256,
                           (t == 0) ? b_fus : nullptr,
                           p_gt + (size_t)t * NDELTA * 512,
                           512, 1, 1024, 1, 512, NDELTA, 512, 256, 1};
        }
        sgemm_b<<<dim3(8, 12, 7), 256>>>(gd);
    }

    // 2) fused qv = q+v_bias, qu = q+u_bias, constD = qv.br per head
    qvqucd_kernel<<<BL, 512>>>(p_q, vb, ub, br, p_qv, p_qu, p_cd);

    // 3) combined: W~ (8 descs, bf16 out) + scoresA (16 descs)
    {
        DescArr24 gd = {};
        // W~[bq,n,f] = sum_d qv[bq, n*64+d] * Wr[n*64+d, f]
        for (int nh = 0; nh < 8; nh++) {
            gd.d[nh] = {p_qv + nh * 64, Wr + (size_t)nh * 64 * 512, nullptr,
                        p_wt + nh * 512,
                        512, 1, 1, 512, 4096, BL, 512, 64, 1};
        }
        // scoresA[b,n,q,k] = sum_d qu[b,q,n*64+d] * k[b,k,n*64+d]
        for (int b2 = 0; b2 < 2; b2++) {
            for (int nh = 0; nh < 8; nh++) {
                int z = 8 + b2 * 8 + nh;
                gd.d[z] = {p_qu + (size_t)b2 * LL * 512 + nh * 64,
                           p_k  + (size_t)b2 * LL * 512 + nh * 64,
                           nullptr,
                           p_sa + (size_t)(b2 * 8 + nh) * LL * LL,
                           512, 1, 512, 1, LL, LL, LL, 64, 0};
            }
        }
        sgemm_b<<<dim3(8, 12, 24), 256>>>(gd);
    }

    // 4) fused attention (bf16 gathers + bf16 W~ dot, softmax, attn@v)
    attn_kernel<<<BL, 256>>>(p_v, p_gt, p_wt, p_sa, p_cd,
                             pos_s, pos_e, seqlp, p_x);

    // 5) final: out = X @ Wff^T + bff
    {
        DescArr24 gd = {};
        gd.d[0] = {p_x, Wff, bff, out, 512, 1, 512, 1, 512, BL, 512, 512, 0};
        sgemm_b<<<dim3(8, 12, 1), 256>>>(gd);
    }
}